// round 9
// baseline (speedup 1.0000x reference)
#include <cuda_runtime.h>
#include <cuda_bf16.h>
#include <cstdint>
#include <cstddef>

#define S_    128
#define B_    64
#define V_    32000
#define E_    32
#define H_    16
#define ROWS  8192
#define NWARP 8
#define WCOLS (V_ / NWARP)      // 4000 cols per warp
#define NGRP  (WCOLS / 8)       // 500 mma groups per warp

// ---------------- device scratch ----------------
__device__ float g_xw[ROWS * H_];
__device__ float g_h[ROWS * H_];
__device__ float g_part[NWARP * ROWS];
__device__ float g_lse[ROWS];

// ---------------- helpers ----------------
__device__ __forceinline__ uint32_t bf16x2_of(float lo, float hi) {
    uint32_t r;
    asm("cvt.rn.bf16x2.f32 %0, %1, %2;" : "=r"(r) : "f"(hi), "f"(lo));
    return r;
}
__device__ __forceinline__ void mma_bf16(float& c0, float& c1, float& c2, float& c3,
                                         const uint32_t a[4], uint32_t b0, uint32_t b1) {
    asm volatile(
        "mma.sync.aligned.m16n8k16.row.col.f32.bf16.bf16.f32 "
        "{%0,%1,%2,%3}, {%4,%5,%6,%7}, {%8,%9}, {%0,%1,%2,%3};"
        : "+f"(c0), "+f"(c1), "+f"(c2), "+f"(c3)
        : "r"(a[0]), "r"(a[1]), "r"(a[2]), "r"(a[3]), "r"(b0), "r"(b1));
}

// ---------------- k1: xw = lookup[idx] @ Wx ----------------
__global__ void k_embed_xw(const int* __restrict__ idx,
                           const float* __restrict__ lookup,
                           const float* __restrict__ wx) {
    __shared__ float sWx[E_ * H_];
    for (int i = threadIdx.x; i < E_ * H_; i += blockDim.x) sWx[i] = wx[i];
    __syncthreads();
    int r = blockIdx.x * blockDim.x + threadIdx.x;
    int id = idx[r];
    float x[E_];
    const float4* lp = reinterpret_cast<const float4*>(lookup + (size_t)id * E_);
    #pragma unroll
    for (int i = 0; i < E_ / 4; i++) {
        float4 t = lp[i];
        x[4*i] = t.x; x[4*i+1] = t.y; x[4*i+2] = t.z; x[4*i+3] = t.w;
    }
    #pragma unroll
    for (int h = 0; h < H_; h++) {
        float a = 0.f;
        #pragma unroll
        for (int e = 0; e < E_; e++) a += x[e] * sWx[e * H_ + h];
        g_xw[r * H_ + h] = a;
    }
}

// ---------------- k2: sequential recurrence ----------------
__global__ void k_rnn(const float* __restrict__ wh, const float* __restrict__ h0) {
    __shared__ float sWh[H_ * H_];
    __shared__ float sh[B_ * H_];
    int tid = threadIdx.x;                 // 1024 threads
    if (tid < H_ * H_) sWh[tid] = wh[tid];
    sh[tid] = h0[tid];
    __syncthreads();
    int b = tid >> 4, j = tid & 15;
    float pre = g_xw[tid];
    for (int s = 0; s < S_; s++) {
        float a = pre;
        float nxt = (s < S_ - 1) ? g_xw[(s + 1) * (B_ * H_) + tid] : 0.f;
        #pragma unroll
        for (int k = 0; k < H_; k++) a += sh[b * H_ + k] * sWh[k * H_ + j];
        float hn = tanhf(a);
        __syncthreads();
        sh[tid] = hn;
        g_h[s * (B_ * H_) + tid] = hn;
        pre = nxt;
        __syncthreads();
    }
}

// ---------------- projection via mma.sync bf16 ----------------
// PASS 0: per-warp expsum partials.  PASS 1: out = logits - lse.
// CTA: 256 thr / 8 warps, 32 rows (2 m-tiles). Warp w owns V-slice [w*4000, ..).
template <int PASS>
__global__ __launch_bounds__(256)
void k_proj(const float* __restrict__ wo, float* __restrict__ out) {
    int tid = threadIdx.x, lane = tid & 31, w = tid >> 5;
    int g = lane >> 2, c = lane & 3;
    int row0 = blockIdx.x * 32;

    // ---- A fragments: rows of h, resident for the whole kernel ----
    uint32_t A[2][4];
    #pragma unroll
    for (int mt = 0; mt < 2; mt++) {
        int r0 = row0 + mt * 16 + g;
        const float* h0 = g_h + (size_t)r0 * H_;
        const float* h8 = g_h + (size_t)(r0 + 8) * H_;
        float2 x0 = *reinterpret_cast<const float2*>(h0 + 2 * c);
        float2 x1 = *reinterpret_cast<const float2*>(h8 + 2 * c);
        float2 x2 = *reinterpret_cast<const float2*>(h0 + 2 * c + 8);
        float2 x3 = *reinterpret_cast<const float2*>(h8 + 2 * c + 8);
        A[mt][0] = bf16x2_of(x0.x, x0.y);
        A[mt][1] = bf16x2_of(x1.x, x1.y);
        A[mt][2] = bf16x2_of(x2.x, x2.y);
        A[mt][3] = bf16x2_of(x3.x, x3.y);
    }

    float nl[2][2];
    if (PASS == 1) {
        #pragma unroll
        for (int mt = 0; mt < 2; mt++) {
            nl[mt][0] = -g_lse[row0 + mt * 16 + g];
            nl[mt][1] = -g_lse[row0 + mt * 16 + g + 8];
        }
    }

    // B pointers: rows k = 2c, 2c+1, 2c+8, 2c+9 of Wo, col = w*4000 + g
    int vcol0 = w * WCOLS + g;
    const float* pa = wo + (size_t)(2 * c) * V_ + vcol0;
    const float* pb = pa + V_;
    const float* pc = pa + (size_t)8 * V_;
    const float* pd = pc + V_;

    float s00 = 0.f, s01 = 0.f, s10 = 0.f, s11 = 0.f;

    float f0 = pa[0], f1 = pb[0], f2 = pc[0], f3 = pd[0];

    #pragma unroll 2
    for (int grp = 0; grp < NGRP; grp++) {
        int nxt = (grp + 1 < NGRP) ? (grp + 1) * 8 : grp * 8;
        float n0 = pa[nxt], n1 = pb[nxt], n2 = pc[nxt], n3 = pd[nxt];

        uint32_t b0 = bf16x2_of(f0, f1);
        uint32_t b1 = bf16x2_of(f2, f3);

        #pragma unroll
        for (int mt = 0; mt < 2; mt++) {
            float c0 = 0.f, c1 = 0.f, c2 = 0.f, c3 = 0.f;
            mma_bf16(c0, c1, c2, c3, A[mt], b0, b1);
            if (PASS == 0) {
                if (mt == 0) {
                    s00 += __expf(c0) + __expf(c1);
                    s01 += __expf(c2) + __expf(c3);
                } else {
                    s10 += __expf(c0) + __expf(c1);
                    s11 += __expf(c2) + __expf(c3);
                }
            } else {
                int col = w * WCOLS + grp * 8 + 2 * c;
                float2 v0 = make_float2(c0 + nl[mt][0], c1 + nl[mt][0]);
                float2 v1 = make_float2(c2 + nl[mt][1], c3 + nl[mt][1]);
                *reinterpret_cast<float2*>(
                    out + (size_t)(row0 + mt * 16 + g) * V_ + col) = v0;
                *reinterpret_cast<float2*>(
                    out + (size_t)(row0 + mt * 16 + g + 8) * V_ + col) = v1;
            }
        }
        f0 = n0; f1 = n1; f2 = n2; f3 = n3;
    }

    if (PASS == 0) {
        // reduce over the 4 lanes sharing a row (lane&3 = 0..3)
        #pragma unroll
        for (int off = 1; off <= 2; off <<= 1) {
            s00 += __shfl_xor_sync(0xffffffffu, s00, off);
            s01 += __shfl_xor_sync(0xffffffffu, s01, off);
            s10 += __shfl_xor_sync(0xffffffffu, s10, off);
            s11 += __shfl_xor_sync(0xffffffffu, s11, off);
        }
        if (c == 0) {
            float* gp = g_part + (size_t)w * ROWS;
            gp[row0 + g]          = s00;
            gp[row0 + g + 8]      = s01;
            gp[row0 + 16 + g]     = s10;
            gp[row0 + 16 + g + 8] = s11;
        }
    }
}

// ---------------- k4: lse = log(sum of partials) ----------------------
__global__ void k_lse_final() {
    int r = blockIdx.x * blockDim.x + threadIdx.x;
    float s = 0.f;
    #pragma unroll
    for (int c = 0; c < NWARP; c++) s += g_part[(size_t)c * ROWS + r];
    g_lse[r] = logf(s);
}

// ---------------- launch --------------------------------------------------
extern "C" void kernel_launch(void* const* d_in, const int* in_sizes, int n_in,
                              void* d_out, int out_size) {
    const int*   idx    = (const int*)  d_in[0];
    const float* lookup = (const float*)d_in[1];
    const float* wx     = (const float*)d_in[2];
    const float* wh     = (const float*)d_in[3];
    const float* wo     = (const float*)d_in[4];
    const float* h0     = (const float*)d_in[5];
    float* out = (float*)d_out;

    k_embed_xw<<<ROWS / 128, 128>>>(idx, lookup, wx);
    k_rnn<<<1, B_ * H_>>>(wh, h0);
    k_proj<0><<<ROWS / 32, 256>>>(wo, nullptr);
    k_lse_final<<<ROWS / 256, 256>>>();
    k_proj<1><<<ROWS / 32, 256>>>(wo, out);
}

// round 10
// speedup vs baseline: 1.1994x; 1.1994x over previous
#include <cuda_runtime.h>
#include <cuda_bf16.h>
#include <cstdint>
#include <cstddef>

#define S_    128
#define B_    64
#define V_    32000
#define E_    32
#define H_    16
#define ROWS  8192
#define NWARP 8
#define WCOLS (V_ / NWARP)      // 4000 cols per warp
#define NGRP  (WCOLS / 8)       // 500 mma groups per warp

// ---------------- device scratch ----------------
__device__ float g_xw[ROWS * H_];
__device__ float g_h[ROWS * H_];
__device__ float g_part[NWARP * ROWS];

// ---------------- helpers ----------------
__device__ __forceinline__ uint32_t bf16x2_of(float lo, float hi) {
    uint32_t r;
    asm("cvt.rn.bf16x2.f32 %0, %1, %2;" : "=r"(r) : "f"(hi), "f"(lo));
    return r;
}
__device__ __forceinline__ void mma_bf16(float& c0, float& c1, float& c2, float& c3,
                                         const uint32_t a[4], uint32_t b0, uint32_t b1) {
    asm volatile(
        "mma.sync.aligned.m16n8k16.row.col.f32.bf16.bf16.f32 "
        "{%0,%1,%2,%3}, {%4,%5,%6,%7}, {%8,%9}, {%0,%1,%2,%3};"
        : "+f"(c0), "+f"(c1), "+f"(c2), "+f"(c3)
        : "r"(a[0]), "r"(a[1]), "r"(a[2]), "r"(a[3]), "r"(b0), "r"(b1));
}

// ---------------- k1: xw = lookup[idx] @ Wx ----------------
__global__ void k_embed_xw(const int* __restrict__ idx,
                           const float* __restrict__ lookup,
                           const float* __restrict__ wx) {
    __shared__ float sWx[E_ * H_];
    for (int i = threadIdx.x; i < E_ * H_; i += blockDim.x) sWx[i] = wx[i];
    __syncthreads();
    int r = blockIdx.x * blockDim.x + threadIdx.x;
    int id = idx[r];
    float x[E_];
    const float4* lp = reinterpret_cast<const float4*>(lookup + (size_t)id * E_);
    #pragma unroll
    for (int i = 0; i < E_ / 4; i++) {
        float4 t = lp[i];
        x[4*i] = t.x; x[4*i+1] = t.y; x[4*i+2] = t.z; x[4*i+3] = t.w;
    }
    #pragma unroll
    for (int h = 0; h < H_; h++) {
        float a = 0.f;
        #pragma unroll
        for (int e = 0; e < E_; e++) a += x[e] * sWx[e * H_ + h];
        g_xw[r * H_ + h] = a;
    }
}

// ---------------- k2: sequential recurrence (ping-pong, 1 sync/step) ----
__global__ void k_rnn(const float* __restrict__ wh, const float* __restrict__ h0) {
    __shared__ float sWh[H_ * H_];
    __shared__ float sh[2][B_ * H_];
    int tid = threadIdx.x;                 // 1024 threads
    if (tid < H_ * H_) sWh[tid] = wh[tid];
    sh[0][tid] = h0[tid];
    __syncthreads();
    int b = tid >> 4, j = tid & 15;
    float pre = g_xw[tid];
    #pragma unroll 2
    for (int s = 0; s < S_; s++) {
        int p = s & 1;
        float a = pre;
        float nxt = (s < S_ - 1) ? g_xw[(s + 1) * (B_ * H_) + tid] : 0.f;
        #pragma unroll
        for (int k = 0; k < H_; k++) a += sh[p][b * H_ + k] * sWh[k * H_ + j];
        float hn = tanhf(a);
        sh[p ^ 1][tid] = hn;
        g_h[s * (B_ * H_) + tid] = hn;
        pre = nxt;
        __syncthreads();
    }
}

// ---------------- projection via mma.sync bf16, depth-4 B prefetch ------
// PASS 0: per-warp expsum partials.  PASS 1: lse (from partials) + write out.
// CTA: 256 thr / 8 warps, 32 rows (2 m-tiles). Warp w owns V-slice [w*4000,..).
template <int PASS>
__global__ __launch_bounds__(256, 2)
void k_proj(const float* __restrict__ wo, float* __restrict__ out) {
    __shared__ float s_nl[32];
    int tid = threadIdx.x, lane = tid & 31, w = tid >> 5;
    int g = lane >> 2, c = lane & 3;
    int row0 = blockIdx.x * 32;

    if (PASS == 1) {
        if (tid < 32) {
            float s = 0.f;
            #pragma unroll
            for (int q = 0; q < NWARP; q++) s += g_part[(size_t)q * ROWS + row0 + tid];
            s_nl[tid] = -logf(s);
        }
        __syncthreads();
    }

    // ---- A fragments: rows of h, resident for the whole kernel ----
    uint32_t A[2][4];
    #pragma unroll
    for (int mt = 0; mt < 2; mt++) {
        int r0 = row0 + mt * 16 + g;
        const float* h0 = g_h + (size_t)r0 * H_;
        const float* h8 = g_h + (size_t)(r0 + 8) * H_;
        float2 x0 = *reinterpret_cast<const float2*>(h0 + 2 * c);
        float2 x1 = *reinterpret_cast<const float2*>(h8 + 2 * c);
        float2 x2 = *reinterpret_cast<const float2*>(h0 + 2 * c + 8);
        float2 x3 = *reinterpret_cast<const float2*>(h8 + 2 * c + 8);
        A[mt][0] = bf16x2_of(x0.x, x0.y);
        A[mt][1] = bf16x2_of(x1.x, x1.y);
        A[mt][2] = bf16x2_of(x2.x, x2.y);
        A[mt][3] = bf16x2_of(x3.x, x3.y);
    }

    float nl[2][2];
    if (PASS == 1) {
        #pragma unroll
        for (int mt = 0; mt < 2; mt++) {
            nl[mt][0] = s_nl[mt * 16 + g];
            nl[mt][1] = s_nl[mt * 16 + g + 8];
        }
    }

    // B pointers: rows k = 2c, 2c+1, 2c+8, 2c+9 of Wo, col = w*4000 + g
    int vcol0 = w * WCOLS + g;
    const float* pa = wo + (size_t)(2 * c) * V_ + vcol0;
    const float* pb = pa + V_;
    const float* pc = pa + (size_t)8 * V_;
    const float* pd = pc + V_;

    float s00 = 0.f, s01 = 0.f, s10 = 0.f, s11 = 0.f;

    // depth-4 rotating prefetch buffer
    float f[4][4];
    #pragma unroll
    for (int d = 0; d < 3; d++) {
        int o = d * 8;                 // NGRP >= 3 always
        f[d][0] = __ldg(pa + o); f[d][1] = __ldg(pb + o);
        f[d][2] = __ldg(pc + o); f[d][3] = __ldg(pd + o);
    }

    #pragma unroll 4
    for (int grp = 0; grp < NGRP; grp++) {
        int ld = grp + 3;
        int o = (ld < NGRP ? ld : NGRP - 1) * 8;
        int q = ld & 3;
        f[q][0] = __ldg(pa + o); f[q][1] = __ldg(pb + o);
        f[q][2] = __ldg(pc + o); f[q][3] = __ldg(pd + o);

        int cu = grp & 3;
        uint32_t b0 = bf16x2_of(f[cu][0], f[cu][1]);
        uint32_t b1 = bf16x2_of(f[cu][2], f[cu][3]);

        #pragma unroll
        for (int mt = 0; mt < 2; mt++) {
            float c0 = 0.f, c1 = 0.f, c2 = 0.f, c3 = 0.f;
            mma_bf16(c0, c1, c2, c3, A[mt], b0, b1);
            if (PASS == 0) {
                if (mt == 0) {
                    s00 += __expf(c0) + __expf(c1);
                    s01 += __expf(c2) + __expf(c3);
                } else {
                    s10 += __expf(c0) + __expf(c1);
                    s11 += __expf(c2) + __expf(c3);
                }
            } else {
                int col = w * WCOLS + grp * 8 + 2 * c;
                float2 v0 = make_float2(c0 + nl[mt][0], c1 + nl[mt][0]);
                float2 v1 = make_float2(c2 + nl[mt][1], c3 + nl[mt][1]);
                *reinterpret_cast<float2*>(
                    out + (size_t)(row0 + mt * 16 + g) * V_ + col) = v0;
                *reinterpret_cast<float2*>(
                    out + (size_t)(row0 + mt * 16 + g + 8) * V_ + col) = v1;
            }
        }
    }

    if (PASS == 0) {
        #pragma unroll
        for (int off = 1; off <= 2; off <<= 1) {
            s00 += __shfl_xor_sync(0xffffffffu, s00, off);
            s01 += __shfl_xor_sync(0xffffffffu, s01, off);
            s10 += __shfl_xor_sync(0xffffffffu, s10, off);
            s11 += __shfl_xor_sync(0xffffffffu, s11, off);
        }
        if (c == 0) {
            float* gp = g_part + (size_t)w * ROWS;
            gp[row0 + g]          = s00;
            gp[row0 + g + 8]      = s01;
            gp[row0 + 16 + g]     = s10;
            gp[row0 + 16 + g + 8] = s11;
        }
    }
}

// ---------------- launch --------------------------------------------------
extern "C" void kernel_launch(void* const* d_in, const int* in_sizes, int n_in,
                              void* d_out, int out_size) {
    const int*   idx    = (const int*)  d_in[0];
    const float* lookup = (const float*)d_in[1];
    const float* wx     = (const float*)d_in[2];
    const float* wh     = (const float*)d_in[3];
    const float* wo     = (const float*)d_in[4];
    const float* h0     = (const float*)d_in[5];
    float* out = (float*)d_out;

    k_embed_xw<<<ROWS / 128, 128>>>(idx, lookup, wx);
    k_rnn<<<1, B_ * H_>>>(wh, h0);
    k_proj<0><<<ROWS / 32, 256>>>(wo, nullptr);
    k_proj<1><<<ROWS / 32, 256>>>(wo, out);
}

// round 11
// speedup vs baseline: 1.3246x; 1.1044x over previous
#include <cuda_runtime.h>
#include <cuda_bf16.h>
#include <cstdint>
#include <cstddef>

#define S_    128
#define B_    64
#define V_    32000
#define E_    32
#define H_    16
#define ROWS  8192
#define VHALF (V_ / 2)          // 16000
#define WCOLS 4000              // cols per warp
#define NGRP  (WCOLS / 16)      // 250 iterations, 16 cols each
#define NPART 8                 // 2 v-chunks x 4 warps

// ---------------- device scratch ----------------
__device__ float g_xw[ROWS * H_];
__device__ float g_h[ROWS * H_];
__device__ float g_part[NPART * ROWS];

// ---------------- helpers ----------------
__device__ __forceinline__ uint32_t bf16x2_of(float lo, float hi) {
    uint32_t r;
    asm("cvt.rn.bf16x2.f32 %0, %1, %2;" : "=r"(r) : "f"(hi), "f"(lo));
    return r;
}
__device__ __forceinline__ void mma_bf16(float& c0, float& c1, float& c2, float& c3,
                                         const uint32_t a[4], uint32_t b0, uint32_t b1) {
    asm volatile(
        "mma.sync.aligned.m16n8k16.row.col.f32.bf16.bf16.f32 "
        "{%0,%1,%2,%3}, {%4,%5,%6,%7}, {%8,%9}, {%0,%1,%2,%3};"
        : "+f"(c0), "+f"(c1), "+f"(c2), "+f"(c3)
        : "r"(a[0]), "r"(a[1]), "r"(a[2]), "r"(a[3]), "r"(b0), "r"(b1));
}

// ---------------- k1: xw = lookup[idx] @ Wx ----------------
__global__ void k_embed_xw(const int* __restrict__ idx,
                           const float* __restrict__ lookup,
                           const float* __restrict__ wx) {
    __shared__ float sWx[E_ * H_];
    for (int i = threadIdx.x; i < E_ * H_; i += blockDim.x) sWx[i] = wx[i];
    __syncthreads();
    int r = blockIdx.x * blockDim.x + threadIdx.x;
    int id = idx[r];
    float x[E_];
    const float4* lp = reinterpret_cast<const float4*>(lookup + (size_t)id * E_);
    #pragma unroll
    for (int i = 0; i < E_ / 4; i++) {
        float4 t = lp[i];
        x[4*i] = t.x; x[4*i+1] = t.y; x[4*i+2] = t.z; x[4*i+3] = t.w;
    }
    #pragma unroll
    for (int h = 0; h < H_; h++) {
        float a = 0.f;
        #pragma unroll
        for (int e = 0; e < E_; e++) a += x[e] * sWx[e * H_ + h];
        g_xw[r * H_ + h] = a;
    }
}

// ---------------- k2: sequential recurrence (ping-pong) ----------------
__global__ void k_rnn(const float* __restrict__ wh, const float* __restrict__ h0) {
    __shared__ float sWh[H_ * H_];
    __shared__ float sh[2][B_ * H_];
    int tid = threadIdx.x;                 // 1024 threads
    if (tid < H_ * H_) sWh[tid] = wh[tid];
    sh[0][tid] = h0[tid];
    __syncthreads();
    int b = tid >> 4, j = tid & 15;
    float pre = g_xw[tid];
    #pragma unroll 2
    for (int s = 0; s < S_; s++) {
        int p = s & 1;
        float a = pre;
        float nxt = (s < S_ - 1) ? g_xw[(s + 1) * (B_ * H_) + tid] : 0.f;
        #pragma unroll
        for (int k = 0; k < H_; k++) a += sh[p][b * H_ + k] * sWh[k * H_ + j];
        float hn = tanhf(a);
        sh[p ^ 1][tid] = hn;
        g_h[s * (B_ * H_) + tid] = hn;
        pre = nxt;
        __syncthreads();
    }
}

// ---------------- projection: mma.sync bf16, 16 rows/CTA, 16 cols/iter ----
// Column permutation: n-tile0 covers real cols m0(g)=2g-(g&1), tile1 m0(g)+2,
// so lane (g,c) accumulates real cols 4c..4c+3 -> float4 stores.
// PASS 0: per-warp expsum partials.  PASS 1: lse from partials + write out.
template <int PASS>
__global__ __launch_bounds__(128, 7)
void k_proj(const float* __restrict__ wo, float* __restrict__ out) {
    __shared__ float s_nl[16];
    int tid = threadIdx.x, lane = tid & 31, w = tid >> 5;
    int g = lane >> 2, c = lane & 3;
    int row0 = blockIdx.x * 16;
    int vbase = blockIdx.y * VHALF + w * WCOLS;

    if (PASS == 1) {
        if (tid < 16) {
            float s = 0.f;
            #pragma unroll
            for (int q = 0; q < NPART; q++) s += g_part[(size_t)q * ROWS + row0 + tid];
            s_nl[tid] = -logf(s);
        }
        __syncthreads();
    }

    // ---- A fragment (one m16 tile), resident all kernel ----
    uint32_t A[4];
    {
        const float* h0 = g_h + (size_t)(row0 + g) * H_;
        const float* h8 = g_h + (size_t)(row0 + g + 8) * H_;
        float2 x0 = *reinterpret_cast<const float2*>(h0 + 2 * c);
        float2 x1 = *reinterpret_cast<const float2*>(h8 + 2 * c);
        float2 x2 = *reinterpret_cast<const float2*>(h0 + 2 * c + 8);
        float2 x3 = *reinterpret_cast<const float2*>(h8 + 2 * c + 8);
        A[0] = bf16x2_of(x0.x, x0.y);
        A[1] = bf16x2_of(x1.x, x1.y);
        A[2] = bf16x2_of(x2.x, x2.y);
        A[3] = bf16x2_of(x3.x, x3.y);
    }

    float nl0 = 0.f, nl1 = 0.f;
    if (PASS == 1) { nl0 = s_nl[g]; nl1 = s_nl[g + 8]; }

    // B row pointers: k = 2c, 2c+1, 2c+8, 2c+9 ; col offsets via permutation
    const float* p0 = wo + (size_t)(2 * c) * V_ + vbase;
    const float* p1 = p0 + V_;
    const float* p2 = p0 + (size_t)8 * V_;
    const float* p3 = p2 + V_;
    int o0 = 2 * g - (g & 1);     // tile0 real col
    int o1 = o0 + 2;              // tile1 real col

    float s0 = 0.f, s1 = 0.f;

    // depth-2 ping-pong prefetch (8 floats/stage)
    float f[2][8];
    f[0][0] = __ldg(p0 + o0); f[0][1] = __ldg(p1 + o0);
    f[0][2] = __ldg(p2 + o0); f[0][3] = __ldg(p3 + o0);
    f[0][4] = __ldg(p0 + o1); f[0][5] = __ldg(p1 + o1);
    f[0][6] = __ldg(p2 + o1); f[0][7] = __ldg(p3 + o1);

    #pragma unroll 2
    for (int grp = 0; grp < NGRP; grp++) {
        int st = grp & 1, ns = st ^ 1;
        int no = (grp + 1 < NGRP ? (grp + 1) * 16 : grp * 16);
        f[ns][0] = __ldg(p0 + no + o0); f[ns][1] = __ldg(p1 + no + o0);
        f[ns][2] = __ldg(p2 + no + o0); f[ns][3] = __ldg(p3 + no + o0);
        f[ns][4] = __ldg(p0 + no + o1); f[ns][5] = __ldg(p1 + no + o1);
        f[ns][6] = __ldg(p2 + no + o1); f[ns][7] = __ldg(p3 + no + o1);

        uint32_t b00 = bf16x2_of(f[st][0], f[st][1]);
        uint32_t b01 = bf16x2_of(f[st][2], f[st][3]);
        uint32_t b10 = bf16x2_of(f[st][4], f[st][5]);
        uint32_t b11 = bf16x2_of(f[st][6], f[st][7]);

        float c0 = 0.f, c1 = 0.f, c2 = 0.f, c3 = 0.f;
        float d0 = 0.f, d1 = 0.f, d2 = 0.f, d3 = 0.f;
        mma_bf16(c0, c1, c2, c3, A, b00, b01);
        mma_bf16(d0, d1, d2, d3, A, b10, b11);

        if (PASS == 0) {
            s0 += __expf(c0) + __expf(c1) + __expf(d0) + __expf(d1);
            s1 += __expf(c2) + __expf(c3) + __expf(d2) + __expf(d3);
        } else {
            int col = vbase + grp * 16 + 4 * c;
            float4 v0 = make_float4(c0 + nl0, c1 + nl0, d0 + nl0, d1 + nl0);
            float4 v1 = make_float4(c2 + nl1, c3 + nl1, d2 + nl1, d3 + nl1);
            *reinterpret_cast<float4*>(out + (size_t)(row0 + g) * V_ + col) = v0;
            *reinterpret_cast<float4*>(out + (size_t)(row0 + g + 8) * V_ + col) = v1;
        }
    }

    if (PASS == 0) {
        #pragma unroll
        for (int off = 1; off <= 2; off <<= 1) {
            s0 += __shfl_xor_sync(0xffffffffu, s0, off);
            s1 += __shfl_xor_sync(0xffffffffu, s1, off);
        }
        if (c == 0) {
            float* gp = g_part + (size_t)(blockIdx.y * 4 + w) * ROWS;
            gp[row0 + g]     = s0;
            gp[row0 + g + 8] = s1;
        }
    }
}

// ---------------- launch --------------------------------------------------
extern "C" void kernel_launch(void* const* d_in, const int* in_sizes, int n_in,
                              void* d_out, int out_size) {
    const int*   idx    = (const int*)  d_in[0];
    const float* lookup = (const float*)d_in[1];
    const float* wx     = (const float*)d_in[2];
    const float* wh     = (const float*)d_in[3];
    const float* wo     = (const float*)d_in[4];
    const float* h0     = (const float*)d_in[5];
    float* out = (float*)d_out;

    k_embed_xw<<<ROWS / 128, 128>>>(idx, lookup, wx);
    k_rnn<<<1, B_ * H_>>>(wh, h0);
    k_proj<0><<<dim3(ROWS / 16, 2), 128>>>(wo, nullptr);
    k_proj<1><<<dim3(ROWS / 16, 2), 128>>>(wo, out);
}